// round 5
// baseline (speedup 1.0000x reference)
#include <cuda_runtime.h>

#define BATCH  4
#define CH     192
#define NPTS   3136
#define KNN    9
#define NSPLIT 3
#define TILE   64
#define NTILES 49            /* 3136/64 */
#define RP_ELEMS (NPTS * NPTS)
#define KC     16            /* channels per k-chunk */
#define NKC    (CH / KC)     /* 12 chunks */

#define POS_INF __int_as_float(0x7f800000)

// ---------------- scratch (device globals; no allocation allowed) ----------
// Kept in the ORIGINAL (b, c, n) layout — no transpose anywhere.
__device__ __align__(16) float g_xn[(size_t)BATCH * CH * NPTS]; // normalized x
__device__ __align__(16) float g_yn[(size_t)BATCH * CH * NPTS]; // normalized y
__device__ float g_x2[BATCH * NPTS];
__device__ float g_y2[BATCH * NPTS];
__device__ float g_pv[BATCH * NPTS * NSPLIT * KNN];
__device__ int   g_pi[BATCH * NPTS * NSPLIT * KNN];

__device__ __forceinline__ bool lex_less(float v, int i, float v2, int i2) {
    return (v < v2) || (v == v2 && i < i2);
}

// sorted insert into register-resident ascending top-KNN list
#define TOPK_INSERT(v, idx, LV, LI)                                        \
  do {                                                                     \
    if (lex_less((v), (idx), LV[KNN-1], LI[KNN-1])) {                      \
      LV[KNN-1] = (v); LI[KNN-1] = (idx);                                  \
      _Pragma("unroll")                                                    \
      for (int _j = KNN-1; _j > 0; --_j) {                                 \
        if (lex_less(LV[_j], LI[_j], LV[_j-1], LI[_j-1])) {                \
          float _tv = LV[_j]; LV[_j] = LV[_j-1]; LV[_j-1] = _tv;           \
          int   _ti = LI[_j]; LI[_j] = LI[_j-1]; LI[_j-1] = _ti;           \
        }                                                                  \
      }                                                                    \
    }                                                                      \
  } while (0)

// ---------- kernel 1: L2-normalize over C (layout preserved), plus x2 ------
__global__ void normalize_kernel(const float* __restrict__ xin,
                                 const float* __restrict__ yin) {
    int sel = blockIdx.z;
    const float* src = sel ? yin : xin;
    float* dst = sel ? g_yn : g_xn;
    float* s2o = sel ? g_y2 : g_x2;
    int b = blockIdx.y;
    int n = blockIdx.x * blockDim.x + threadIdx.x;
    if (n >= NPTS) return;

    const float* sb = src + (size_t)b * CH * NPTS + n;
    float s = 0.f;
    #pragma unroll 8
    for (int c = 0; c < CH; c++) {
        float v = sb[(size_t)c * NPTS];
        s += v * v;
    }
    float dn = fmaxf(sqrtf(s), 1e-12f);

    float* db = dst + (size_t)b * CH * NPTS + n;
    float x2 = 0.f;
    #pragma unroll 8
    for (int c = 0; c < CH; c++) {
        float v = sb[(size_t)c * NPTS] / dn;
        db[(size_t)c * NPTS] = v;
        x2 += v * v;
    }
    s2o[b * NPTS + n] = x2;
}

// -------- kernel 2: TN-SGEMM 64x64 tiles (K chunked) + streaming top-9 -----
__global__ void __launch_bounds__(256, 2)
knn_kernel(const float* __restrict__ rp) {
    __shared__ __align__(16) float xs[KC * TILE];   //  4 KB [chan][point]
    __shared__ __align__(16) float ys[KC * TILE];   //  4 KB
    __shared__ float ds[TILE * 65];                 // 16.6 KB
    __shared__ float cv[TILE * 36];                 //  9.2 KB
    __shared__ int   ci[TILE * 36];                 //  9.2 KB
    __shared__ float x2s[TILE], y2s[TILE];          //  0.5 KB  (total 43.8KB)

    int b     = blockIdx.z;
    int split = blockIdx.y;
    int n0    = blockIdx.x * TILE;

    int tid = threadIdx.x;
    int tx  = tid & 15;          // micro-tile col group
    int ty  = tid >> 4;          // micro-tile row group
    int c_l = tid >> 4;          // loader: channel within chunk (0..15)
    int n4  = (tid & 15) * 4;    // loader: point offset (0..60)

    if (tid < TILE) x2s[tid] = g_x2[b * NPTS + n0 + tid];

    float bvK[KNN]; int biK[KNN];
    #pragma unroll
    for (int j = 0; j < KNN; j++) { bvK[j] = POS_INF; biK[j] = 0x7FFFFFFF; }

    int t_lo = (split == 0) ? 0  : (split == 1 ? 17 : 33);
    int t_hi = (split == 0) ? 17 : (split == 1 ? 33 : 49);

    const float* xb = g_xn + (size_t)b * CH * NPTS + n0;  // x cols fixed at n0
    const float* yb = g_yn + (size_t)b * CH * NPTS;

    // prefetch first chunk (mt = t_lo, kc = 0)
    float4 px = *(const float4*)(xb + (size_t)c_l * NPTS + n4);
    float4 py = *(const float4*)(yb + (size_t)c_l * NPTS + t_lo * TILE + n4);

    for (int mt = t_lo; mt < t_hi; mt++) {
        int m0 = mt * TILE;

        float acc[4][4];
        #pragma unroll
        for (int i = 0; i < 4; i++)
            #pragma unroll
            for (int j = 0; j < 4; j++) acc[i][j] = 0.f;

        for (int kc = 0; kc < NKC; kc++) {
            __syncthreads();   // smem free (prev chunk consumed / prev scan done)
            *(float4*)&xs[c_l * TILE + n4] = px;
            *(float4*)&ys[c_l * TILE + n4] = py;
            if (kc == 0 && tid < TILE) y2s[tid] = g_y2[b * NPTS + m0 + tid];
            __syncthreads();

            // prefetch next chunk (possibly next m-tile)
            int nkc = kc + 1, nmt = mt;
            if (nkc == NKC) { nkc = 0; nmt = mt + 1; }
            if (nmt < t_hi) {
                px = *(const float4*)(xb + (size_t)(nkc * KC + c_l) * NPTS + n4);
                py = *(const float4*)(yb + (size_t)(nkc * KC + c_l) * NPTS
                                        + nmt * TILE + n4);
            }

            #pragma unroll
            for (int ku = 0; ku < KC; ku++) {
                float4 av = *(const float4*)&xs[ku * TILE + ty * 4];
                float4 bw = *(const float4*)&ys[ku * TILE + tx * 4];
                float a[4] = {av.x, av.y, av.z, av.w};
                float w[4] = {bw.x, bw.y, bw.z, bw.w};
                #pragma unroll
                for (int i = 0; i < 4; i++)
                    #pragma unroll
                    for (int j = 0; j < 4; j++)
                        acc[i][j] += a[i] * w[j];
            }
        }

        // epilogue: dist = sqrt(max(x2+y2-2xy,0)) + relative_pos
        #pragma unroll
        for (int i = 0; i < 4; i++) {
            int row = ty * 4 + i;
            int n   = n0 + row;
            float x2v = x2s[row];
            const float* rpr = rp + (size_t)n * NPTS + m0;
            #pragma unroll
            for (int j = 0; j < 4; j++) {
                int col = tx * 4 + j;
                float d2 = (x2v + y2s[col]) - 2.0f * acc[i][j];
                float d  = sqrtf(fmaxf(d2, 0.0f)) + rpr[col];
                ds[row * 65 + col] = d;
            }
        }
        __syncthreads();

        // scan: 4 threads per row, 16 cols each, register top-9
        {
            int srow = tid & 63, slot = tid >> 6;
            int cb = slot * 16;
            #pragma unroll
            for (int c = 0; c < 16; c++) {
                float v  = ds[srow * 65 + cb + c];
                int  idx = m0 + cb + c;
                TOPK_INSERT(v, idx, bvK, biK);
            }
        }
        // next loop's first __syncthreads() protects ds before overwrite
    }
    __syncthreads();

    // dump per-thread candidates and merge 4 slots -> 9 per row
    {
        int srow = tid & 63, slot = tid >> 6;
        #pragma unroll
        for (int j = 0; j < KNN; j++) {
            cv[srow * 36 + slot * 9 + j] = bvK[j];
            ci[srow * 36 + slot * 9 + j] = biK[j];
        }
    }
    __syncthreads();
    if (tid < TILE) {
        float mv[KNN]; int mi[KNN];
        #pragma unroll
        for (int j = 0; j < KNN; j++) { mv[j] = POS_INF; mi[j] = 0x7FFFFFFF; }
        for (int t = 0; t < 36; t++) {
            float v = cv[tid * 36 + t]; int ii = ci[tid * 36 + t];
            TOPK_INSERT(v, ii, mv, mi);
        }
        size_t base = ((size_t)(b * NPTS + n0 + tid) * NSPLIT + split) * KNN;
        #pragma unroll
        for (int j = 0; j < KNN; j++) { g_pv[base + j] = mv[j]; g_pi[base + j] = mi[j]; }
    }
}

// --------- kernel 3: merge splits, emit (2,B,N,K) as FLOAT32 --------------
// The harness output dtype is float32 (jax reference indices are cast for
// comparison) — writing raw int bit patterns reads back as denormals ~= 0
// and yields rel_err == 1.0 exactly. Convert indices to float here.
__global__ void knn_finalize(float* __restrict__ out) {
    int gid = blockIdx.x * blockDim.x + threadIdx.x;  // b*NPTS + n
    if (gid >= BATCH * NPTS) return;
    float mv[KNN]; int mi[KNN];
    #pragma unroll
    for (int j = 0; j < KNN; j++) { mv[j] = POS_INF; mi[j] = 0x7FFFFFFF; }
    size_t base = (size_t)gid * NSPLIT * KNN;
    for (int t = 0; t < NSPLIT * KNN; t++) {
        float v = g_pv[base + t]; int ii = g_pi[base + t];
        TOPK_INSERT(v, ii, mv, mi);
    }
    int n = gid % NPTS;
    float* o0 = out + (size_t)gid * KNN;                              // nn_idx
    float* o1 = out + (size_t)BATCH * NPTS * KNN + (size_t)gid * KNN; // center
    #pragma unroll
    for (int j = 0; j < KNN; j++) {
        o0[j] = (float)mi[j];
        o1[j] = (float)n;
    }
}

// --------------------------------- launch ---------------------------------
extern "C" void kernel_launch(void* const* d_in, const int* in_sizes, int n_in,
                              void* d_out, int out_size) {
    // Robust input dispatch: relative_pos is uniquely NPTS*NPTS elements;
    // x and y (equal sizes) keep their relative order.
    const float* x  = nullptr;
    const float* y  = nullptr;
    const float* rp = nullptr;
    for (int i = 0; i < n_in; i++) {
        if (in_sizes[i] == RP_ELEMS && rp == nullptr) {
            rp = (const float*)d_in[i];
        } else if (x == nullptr) {
            x = (const float*)d_in[i];
        } else if (y == nullptr) {
            y = (const float*)d_in[i];
        }
    }
    if (!x || !y || !rp) return;
    float* out = (float*)d_out;

    dim3 g1((NPTS + 255) / 256, BATCH, 2);
    normalize_kernel<<<g1, 256>>>(x, y);

    dim3 g2(NTILES, NSPLIT, BATCH);
    knn_kernel<<<g2, 256>>>(rp);

    knn_finalize<<<(BATCH * NPTS + 127) / 128, 128>>>(out);
}

// round 6
// speedup vs baseline: 1.2032x; 1.2032x over previous
#include <cuda_runtime.h>

#define BATCH  4
#define CH     192
#define NPTS   3136
#define KNN    9
#define NSPLIT 3
#define TILE   64
#define NTILES 49            /* 3136/64 */
#define RP_ELEMS (NPTS * NPTS)
#define KC     16            /* channels per k-chunk */
#define NKC    (CH / KC)     /* 12 chunks */

#define POS_INF __int_as_float(0x7f800000)

// ---------------- scratch (device globals; no allocation allowed) ----------
// Kept in the ORIGINAL (b, c, n) layout — no transpose anywhere.
__device__ __align__(16) float g_xn[(size_t)BATCH * CH * NPTS]; // normalized x
__device__ __align__(16) float g_yn[(size_t)BATCH * CH * NPTS]; // normalized y
__device__ __align__(16) float g_x2[BATCH * NPTS];
__device__ __align__(16) float g_y2[BATCH * NPTS];
__device__ float g_pv[BATCH * NPTS * NSPLIT * KNN];
__device__ int   g_pi[BATCH * NPTS * NSPLIT * KNN];

__device__ __forceinline__ bool lex_less(float v, int i, float v2, int i2) {
    return (v < v2) || (v == v2 && i < i2);
}

// sorted insert into register-resident ascending top-KNN list
#define TOPK_INSERT(v, idx, LV, LI)                                        \
  do {                                                                     \
    if (lex_less((v), (idx), LV[KNN-1], LI[KNN-1])) {                      \
      LV[KNN-1] = (v); LI[KNN-1] = (idx);                                  \
      _Pragma("unroll")                                                    \
      for (int _j = KNN-1; _j > 0; --_j) {                                 \
        if (lex_less(LV[_j], LI[_j], LV[_j-1], LI[_j-1])) {                \
          float _tv = LV[_j]; LV[_j] = LV[_j-1]; LV[_j-1] = _tv;           \
          int   _ti = LI[_j]; LI[_j] = LI[_j-1]; LI[_j-1] = _ti;           \
        }                                                                  \
      }                                                                    \
    }                                                                      \
  } while (0)

// ---------- kernel 1: L2-normalize over C (layout preserved), plus x2 ------
// 32 points x 8 channel-groups per block: 8x fewer serial loads per thread,
// 784 blocks instead of 104 (latency-bound fix).
__global__ void normalize_kernel(const float* __restrict__ xin,
                                 const float* __restrict__ yin) {
    int sel = blockIdx.z;
    const float* src = sel ? yin : xin;
    float* dst = sel ? g_yn : g_xn;
    float* s2o = sel ? g_y2 : g_x2;
    int b  = blockIdx.y;
    int tx = threadIdx.x;                 // point within 32-tile
    int ty = threadIdx.y;                 // channel group (0..7)
    int n  = blockIdx.x * 32 + tx;

    __shared__ float red[8][33];

    const float* sb = src + (size_t)b * CH * NPTS + n;
    float acc = 0.f;
    #pragma unroll
    for (int c = ty; c < CH; c += 8) {
        float v = sb[(size_t)c * NPTS];
        acc += v * v;
    }
    red[ty][tx] = acc;
    __syncthreads();
    float s = red[0][tx];
    #pragma unroll
    for (int j = 1; j < 8; j++) s += red[j][tx];
    float dn = fmaxf(sqrtf(s), 1e-12f);

    float* db = dst + (size_t)b * CH * NPTS + n;
    float acc2 = 0.f;
    #pragma unroll
    for (int c = ty; c < CH; c += 8) {
        float v = sb[(size_t)c * NPTS] / dn;
        db[(size_t)c * NPTS] = v;
        acc2 += v * v;
    }
    __syncthreads();           // red free
    red[ty][tx] = acc2;
    __syncthreads();
    if (ty == 0) {
        float s2 = red[0][tx];
        #pragma unroll
        for (int j = 1; j < 8; j++) s2 += red[j][tx];
        s2o[b * NPTS + n] = s2;
    }
}

// -------- kernel 2: TN-SGEMM 64x64 tiles, double-buffered K chunks ---------
// One __syncthreads per chunk. Candidate-merge arrays alias the (dead)
// GEMM buffers via union. 35.6KB static smem -> 4 blocks/SM = 1 full wave.
__global__ void __launch_bounds__(256, 4)
knn_kernel(const float* __restrict__ rp) {
    __shared__ union {
        struct {
            float xs[2][KC * TILE];     // 2 x 4 KB
            float ys[2][KC * TILE];     // 2 x 4 KB
        } t;                            // 16 KB
        struct {
            float cv[TILE * 36];
            int   ci[TILE * 36];
        } c;                            // 18.4 KB
    } shr;
    __shared__ float ds[TILE * 65];     // 16.6 KB
    __shared__ float x2s[TILE];         // 256 B   (total ~35.6 KB)

    int b     = blockIdx.z;
    int split = blockIdx.y;
    int n0    = blockIdx.x * TILE;

    int tid = threadIdx.x;
    int tx  = tid & 15;          // micro-tile col group
    int ty  = tid >> 4;          // micro-tile row group
    int c_l = tid >> 4;          // loader: channel within chunk (0..15)
    int n4  = (tid & 15) * 4;    // loader: point offset (0..60)

    float bvK[KNN]; int biK[KNN];
    #pragma unroll
    for (int j = 0; j < KNN; j++) { bvK[j] = POS_INF; biK[j] = 0x7FFFFFFF; }

    int t_lo = (split == 0) ? 0  : (split == 1 ? 17 : 33);
    int t_hi = (split == 0) ? 17 : (split == 1 ? 33 : 49);

    const float* xb = g_xn + (size_t)b * CH * NPTS + n0;
    const float* yb = g_yn + (size_t)b * CH * NPTS;

    // prologue: load chunk (t_lo, 0) into buffer 0
    {
        float4 px = *(const float4*)(xb + (size_t)c_l * NPTS + n4);
        float4 py = *(const float4*)(yb + (size_t)c_l * NPTS + t_lo * TILE + n4);
        *(float4*)&shr.t.xs[0][c_l * TILE + n4] = px;
        *(float4*)&shr.t.ys[0][c_l * TILE + n4] = py;
    }
    if (tid < TILE) x2s[tid] = g_x2[b * NPTS + n0 + tid];
    __syncthreads();

    int p = 0;
    for (int mt = t_lo; mt < t_hi; mt++) {
        int m0 = mt * TILE;

        float acc[4][4];
        #pragma unroll
        for (int i = 0; i < 4; i++)
            #pragma unroll
            for (int j = 0; j < 4; j++) acc[i][j] = 0.f;

        for (int kc = 0; kc < NKC; kc++) {
            // prefetch next chunk (possibly next m-tile) into registers
            int nkc = kc + 1, nmt = mt;
            if (nkc == NKC) { nkc = 0; nmt = mt + 1; }
            bool has_next = (nmt < t_hi);
            float4 px, py;
            if (has_next) {
                px = *(const float4*)(xb + (size_t)(nkc * KC + c_l) * NPTS + n4);
                py = *(const float4*)(yb + (size_t)(nkc * KC + c_l) * NPTS
                                        + nmt * TILE + n4);
            }

            // compute on current buffer (hides the LDG latency above)
            const float* xsp = shr.t.xs[p];
            const float* ysp = shr.t.ys[p];
            #pragma unroll
            for (int ku = 0; ku < KC; ku++) {
                float4 av = *(const float4*)&xsp[ku * TILE + ty * 4];
                float4 bw = *(const float4*)&ysp[ku * TILE + tx * 4];
                float a[4] = {av.x, av.y, av.z, av.w};
                float w[4] = {bw.x, bw.y, bw.z, bw.w};
                #pragma unroll
                for (int i = 0; i < 4; i++)
                    #pragma unroll
                    for (int j = 0; j < 4; j++)
                        acc[i][j] += a[i] * w[j];
            }

            // stage next chunk into the other buffer (consumed 1 iter ago)
            if (has_next) {
                *(float4*)&shr.t.xs[p ^ 1][c_l * TILE + n4] = px;
                *(float4*)&shr.t.ys[p ^ 1][c_l * TILE + n4] = py;
            }
            __syncthreads();
            p ^= 1;
        }

        // epilogue: dist = sqrt(max(x2+y2-2xy,0)) + relative_pos
        float4 y2v = *(const float4*)(g_y2 + b * NPTS + m0 + tx * 4);
        float y2a[4] = {y2v.x, y2v.y, y2v.z, y2v.w};
        #pragma unroll
        for (int i = 0; i < 4; i++) {
            int row = ty * 4 + i;
            int n   = n0 + row;
            float x2v = x2s[row];
            const float* rpr = rp + (size_t)n * NPTS + m0;
            #pragma unroll
            for (int j = 0; j < 4; j++) {
                int col = tx * 4 + j;
                float d2 = (x2v + y2a[j]) - 2.0f * acc[i][j];
                float d  = sqrtf(fmaxf(d2, 0.0f)) + rpr[col];
                ds[row * 65 + col] = d;
            }
        }
        __syncthreads();

        // scan: 4 threads per row, 16 cols each, register top-9
        {
            int srow = tid & 63, slot = tid >> 6;
            int cb = slot * 16;
            #pragma unroll
            for (int c = 0; c < 16; c++) {
                float v  = ds[srow * 65 + cb + c];
                int  idx = m0 + cb + c;
                TOPK_INSERT(v, idx, bvK, biK);
            }
        }
        // next m-tile's chunk-loop barriers protect ds before overwrite
    }
    __syncthreads();

    // dump per-thread candidates (aliases dead GEMM buffers) and merge
    {
        int srow = tid & 63, slot = tid >> 6;
        #pragma unroll
        for (int j = 0; j < KNN; j++) {
            shr.c.cv[srow * 36 + slot * 9 + j] = bvK[j];
            shr.c.ci[srow * 36 + slot * 9 + j] = biK[j];
        }
    }
    __syncthreads();
    if (tid < TILE) {
        float mv[KNN]; int mi[KNN];
        #pragma unroll
        for (int j = 0; j < KNN; j++) { mv[j] = POS_INF; mi[j] = 0x7FFFFFFF; }
        for (int t = 0; t < 36; t++) {
            float v = shr.c.cv[tid * 36 + t]; int ii = shr.c.ci[tid * 36 + t];
            TOPK_INSERT(v, ii, mv, mi);
        }
        size_t base = ((size_t)(b * NPTS + n0 + tid) * NSPLIT + split) * KNN;
        #pragma unroll
        for (int j = 0; j < KNN; j++) { g_pv[base + j] = mv[j]; g_pi[base + j] = mi[j]; }
    }
}

// --------- kernel 3: merge splits, emit (2,B,N,K) as FLOAT32 --------------
__global__ void knn_finalize(float* __restrict__ out) {
    int gid = blockIdx.x * blockDim.x + threadIdx.x;  // b*NPTS + n
    if (gid >= BATCH * NPTS) return;
    float mv[KNN]; int mi[KNN];
    #pragma unroll
    for (int j = 0; j < KNN; j++) { mv[j] = POS_INF; mi[j] = 0x7FFFFFFF; }
    size_t base = (size_t)gid * NSPLIT * KNN;
    for (int t = 0; t < NSPLIT * KNN; t++) {
        float v = g_pv[base + t]; int ii = g_pi[base + t];
        TOPK_INSERT(v, ii, mv, mi);
    }
    int n = gid % NPTS;
    float* o0 = out + (size_t)gid * KNN;                              // nn_idx
    float* o1 = out + (size_t)BATCH * NPTS * KNN + (size_t)gid * KNN; // center
    #pragma unroll
    for (int j = 0; j < KNN; j++) {
        o0[j] = (float)mi[j];
        o1[j] = (float)n;
    }
}

// --------------------------------- launch ---------------------------------
extern "C" void kernel_launch(void* const* d_in, const int* in_sizes, int n_in,
                              void* d_out, int out_size) {
    // Robust input dispatch: relative_pos is uniquely NPTS*NPTS elements;
    // x and y (equal sizes) keep their relative order.
    const float* x  = nullptr;
    const float* y  = nullptr;
    const float* rp = nullptr;
    for (int i = 0; i < n_in; i++) {
        if (in_sizes[i] == RP_ELEMS && rp == nullptr) {
            rp = (const float*)d_in[i];
        } else if (x == nullptr) {
            x = (const float*)d_in[i];
        } else if (y == nullptr) {
            y = (const float*)d_in[i];
        }
    }
    if (!x || !y || !rp) return;
    float* out = (float*)d_out;

    dim3 g1(NPTS / 32, BATCH, 2), b1(32, 8);
    normalize_kernel<<<g1, b1>>>(x, y);

    dim3 g2(NTILES, NSPLIT, BATCH);
    knn_kernel<<<g2, 256>>>(rp);

    knn_finalize<<<(BATCH * NPTS + 127) / 128, 128>>>(out);
}